// round 2
// baseline (speedup 1.0000x reference)
#include <cuda_runtime.h>
#include <math.h>

#define NMAX 100000
#define EMAX 1600000
#define CIN  64

// ---------------- device scratch (no allocation allowed) ----------------
__device__ int   g_is64;
__device__ int   g_src[EMAX];
__device__ int   g_dst[EMAX];
__device__ float g_deg[NMAX];                       // becomes invdeg after k_invdeg
__device__ __align__(256) float g_agg[(size_t)NMAX * 64];
__device__ __align__(256) float g_h0[(size_t)NMAX * 64];
__device__ __align__(256) float g_h1[(size_t)NMAX * 64];
__device__ float g_stats[128];                      // [sum(64) | sumsq(64)]
__device__ float g_affine[128];                     // [scale(64) | shift(64)]

// ---------------- dtype detection ----------------
// If edge_index is int64 (values in [0,1e5), nonnegative), every odd 32-bit
// word of the buffer is 0. If int32, odd words are real indices (P(all 2048
// checked == 0) ~ 1e-5^2048 -> effectively zero).
__global__ void k_detect(const unsigned int* __restrict__ w) {
    int i = threadIdx.x;  // 1024 threads, check 2048 odd words
    int ok = (w[2 * i + 1] == 0u) && (w[2 * (i + 1024) + 1] == 0u);
    int all = __syncthreads_and(ok);
    if (i == 0) g_is64 = all ? 1 : 0;
}

__global__ void k_zero_deg(int N) {
    int i = blockIdx.x * blockDim.x + threadIdx.x;
    if (i < N) g_deg[i] = 0.0f;
}

// decode edge index to int32 src/dst + accumulate degree
__global__ void k_decode(const void* __restrict__ ei, int E) {
    int i = blockIdx.x * blockDim.x + threadIdx.x;
    if (i >= E) return;
    int s, d;
    if (g_is64) {
        const long long* p = (const long long*)ei;
        s = (int)p[i];
        d = (int)p[E + i];
    } else {
        const int* p = (const int*)ei;
        s = p[i];
        d = p[E + i];
    }
    g_src[i] = s;
    g_dst[i] = d;
    asm volatile("red.global.add.f32 [%0], %1;" :: "l"(&g_deg[d]), "f"(1.0f) : "memory");
}

__global__ void k_invdeg(int N) {
    int i = blockIdx.x * blockDim.x + threadIdx.x;
    if (i < N) g_deg[i] = 1.0f / fmaxf(g_deg[i], 1.0f);
}

__global__ void k_zero_agg(int n) {
    int i = blockIdx.x * blockDim.x + threadIdx.x;
    if (i < n) g_agg[i] = 0.0f;
}

// ---------------- edge aggregation: agg[dst] += x[src], vectorized red.v4 ----------------
__global__ void __launch_bounds__(256) k_aggregate(const float* __restrict__ x, int E) {
    int t = blockIdx.x * 256 + threadIdx.x;          // E*16 work items
    if (t >= E * 16) return;
    int e = t >> 4;
    int c = (t & 15) << 2;                           // float offset, 16B aligned
    int s = g_src[e];
    int d = g_dst[e];
    const float4 v = *reinterpret_cast<const float4*>(x + (size_t)s * 64 + c);
    asm volatile("red.global.add.v4.f32 [%0], {%1,%2,%3,%4};"
                 :: "l"(g_agg + (size_t)d * 64 + c),
                    "f"(v.x), "f"(v.y), "f"(v.z), "f"(v.w)
                 : "memory");
}

// ---------------- fused SAGE linear: out = (agg*invdeg)@Wl + x@Wr + b ----------------
// 4 nodes x 4 output channels per thread (16 accumulators).
template <int COUT, bool STATS>
__global__ void __launch_bounds__((COUT / 4) * 16)
k_sage_mm(const float* __restrict__ x,
          const float* __restrict__ Wl,
          const float* __restrict__ Wr,
          const float* __restrict__ bias,
          float* __restrict__ out,
          int N) {
    constexpr int CQ = COUT / 4;        // channel groups (16 or 10)
    constexpr int NT = 64;              // node tile
    constexpr int THREADS = CQ * 16;
    constexpr int RS = CIN + 4;         // padded row stride (bank-conflict-free)

    extern __shared__ float smem[];
    float* sM  = smem;                  // NT*RS
    float* sX  = sM + NT * RS;          // NT*RS
    float* sWl = sX + NT * RS;          // CIN*COUT
    float* sWr = sWl + CIN * COUT;      // CIN*COUT
    float* sSum = sWr + CIN * COUT;     // COUT
    float* sSq  = sSum + COUT;          // COUT

    int tid = threadIdx.x;
    for (int i = tid; i < CIN * COUT; i += THREADS) {
        sWl[i] = Wl[i];
        sWr[i] = Wr[i];
    }
    if (STATS) {
        for (int i = tid; i < COUT; i += THREADS) { sSum[i] = 0.0f; sSq[i] = 0.0f; }
    }

    int tile = blockIdx.x * NT;
    // stage node rows (float4), apply invdeg to the aggregate during staging
    for (int q = tid; q < NT * (CIN / 4); q += THREADS) {
        int row = q / (CIN / 4);
        int c4  = (q % (CIN / 4)) * 4;
        int n = tile + row;
        float4 mv, xv;
        if (n < N) {
            float inv = g_deg[n];
            mv = *reinterpret_cast<const float4*>(g_agg + (size_t)n * CIN + c4);
            mv.x *= inv; mv.y *= inv; mv.z *= inv; mv.w *= inv;
            xv = *reinterpret_cast<const float4*>(x + (size_t)n * CIN + c4);
        } else {
            mv = make_float4(0.f, 0.f, 0.f, 0.f);
            xv = mv;
        }
        *reinterpret_cast<float4*>(sM + row * RS + c4) = mv;
        *reinterpret_cast<float4*>(sX + row * RS + c4) = xv;
    }
    __syncthreads();

    int cog = tid % CQ;
    int ng  = tid / CQ;        // 0..15
    int nb  = ng * 4;

    float acc[4][4];
#pragma unroll
    for (int j = 0; j < 4; j++) {
        float b = bias[cog + j * CQ];
#pragma unroll
        for (int i = 0; i < 4; i++) acc[i][j] = b;
    }

#pragma unroll 4
    for (int k = 0; k < CIN; k++) {
        float wl[4], wr[4], m[4], xr[4];
#pragma unroll
        for (int j = 0; j < 4; j++) {
            wl[j] = sWl[k * COUT + cog + j * CQ];
            wr[j] = sWr[k * COUT + cog + j * CQ];
        }
#pragma unroll
        for (int i = 0; i < 4; i++) {
            m[i]  = sM[(nb + i) * RS + k];
            xr[i] = sX[(nb + i) * RS + k];
        }
#pragma unroll
        for (int i = 0; i < 4; i++)
#pragma unroll
            for (int j = 0; j < 4; j++)
                acc[i][j] += m[i] * wl[j] + xr[i] * wr[j];
    }

    float lsum[4] = {0.f, 0.f, 0.f, 0.f};
    float lsq[4]  = {0.f, 0.f, 0.f, 0.f};
#pragma unroll
    for (int i = 0; i < 4; i++) {
        int n = tile + nb + i;
        if (n < N) {
#pragma unroll
            for (int j = 0; j < 4; j++) {
                float v = acc[i][j];
                out[(size_t)n * COUT + cog + j * CQ] = v;
                if (STATS) { lsum[j] += v; lsq[j] += v * v; }
            }
        }
    }

    if (STATS) {
#pragma unroll
        for (int j = 0; j < 4; j++) {
            atomicAdd(&sSum[cog + j * CQ], lsum[j]);
            atomicAdd(&sSq[cog + j * CQ],  lsq[j]);
        }
        __syncthreads();
        for (int c = tid; c < COUT; c += THREADS) {
            atomicAdd(&g_stats[c],      sSum[c]);
            atomicAdd(&g_stats[64 + c], sSq[c]);
        }
    }
}

__global__ void k_zero_stats() {
    int i = threadIdx.x;
    if (i < 128) g_stats[i] = 0.0f;
}

__global__ void k_bn_finalize(const float* __restrict__ g, const float* __restrict__ be,
                              float invN) {
    int c = threadIdx.x;
    if (c < 64) {
        float mu  = g_stats[c] * invN;
        float var = g_stats[64 + c] * invN - mu * mu;
        float a = g[c] * rsqrtf(var + 1e-5f);
        g_affine[c] = a;
        g_affine[64 + c] = be[c] - mu * a;
    }
}

__global__ void k_bn_relu(float* __restrict__ h, int n) {
    int i = blockIdx.x * blockDim.x + threadIdx.x;
    if (i < n) {
        int c = i & 63;
        h[i] = fmaxf(fmaf(h[i], g_affine[c], g_affine[64 + c]), 0.0f);
    }
}

// ---------------- launch ----------------
extern "C" void kernel_launch(void* const* d_in, const int* in_sizes, int n_in,
                              void* d_out, int out_size) {
    const float* x   = (const float*)d_in[0];
    const void*  ei  = d_in[1];
    const float* Wl0 = (const float*)d_in[2];
    const float* Wr0 = (const float*)d_in[3];
    const float* b0  = (const float*)d_in[4];
    const float* Wl1 = (const float*)d_in[5];
    const float* Wr1 = (const float*)d_in[6];
    const float* b1  = (const float*)d_in[7];
    const float* Wl2 = (const float*)d_in[8];
    const float* Wr2 = (const float*)d_in[9];
    const float* b2  = (const float*)d_in[10];
    const float* g0  = (const float*)d_in[11];
    const float* be0 = (const float*)d_in[12];
    const float* g1  = (const float*)d_in[13];
    const float* be1 = (const float*)d_in[14];
    float* out = (float*)d_out;

    int N = in_sizes[0] / 64;
    int E = in_sizes[1] / 2;

    float *h0p, *h1p;
    cudaGetSymbolAddress((void**)&h0p, g_h0);
    cudaGetSymbolAddress((void**)&h1p, g_h1);

    // opt-in shared memory for the GEMM kernels (every call; idempotent)
    const int smem64 = (2 * 64 * (CIN + 4) + 2 * CIN * 64 + 2 * 64) * 4;
    const int smem40 = (2 * 64 * (CIN + 4) + 2 * CIN * 40 + 2 * 40) * 4;
    cudaFuncSetAttribute(k_sage_mm<64, true>,
                         cudaFuncAttributeMaxDynamicSharedMemorySize, smem64);
    cudaFuncSetAttribute(k_sage_mm<40, false>,
                         cudaFuncAttributeMaxDynamicSharedMemorySize, smem40);

    const int nodeBlocks = (N + 255) / 256;
    const int edgeBlocks = (E + 255) / 256;
    const int aggElems   = N * 64;
    const int aggZeroBlocks = (aggElems + 255) / 256;
    const int aggBlocks  = (E * 16 + 255) / 256;
    const int mmGrid     = (N + 63) / 64;
    const int ewBlocks   = (N * 64 + 255) / 256;

    // preprocessing
    k_detect<<<1, 1024>>>((const unsigned int*)ei);
    k_zero_deg<<<nodeBlocks, 256>>>(N);
    k_decode<<<edgeBlocks, 256>>>(ei, E);
    k_invdeg<<<nodeBlocks, 256>>>(N);

    // ---- layer 0 ----
    k_zero_agg<<<aggZeroBlocks, 256>>>(aggElems);
    k_aggregate<<<aggBlocks, 256>>>(x, E);
    k_zero_stats<<<1, 128>>>();
    k_sage_mm<64, true><<<mmGrid, 256, smem64>>>(x, Wl0, Wr0, b0, h0p, N);
    k_bn_finalize<<<1, 64>>>(g0, be0, 1.0f / (float)N);
    k_bn_relu<<<ewBlocks, 256>>>(h0p, N * 64);

    // ---- layer 1 ----
    k_zero_agg<<<aggZeroBlocks, 256>>>(aggElems);
    k_aggregate<<<aggBlocks, 256>>>(h0p, E);
    k_zero_stats<<<1, 128>>>();
    k_sage_mm<64, true><<<mmGrid, 256, smem64>>>(h0p, Wl1, Wr1, b1, h1p, N);
    k_bn_finalize<<<1, 64>>>(g1, be1, 1.0f / (float)N);
    k_bn_relu<<<ewBlocks, 256>>>(h1p, N * 64);

    // ---- layer 2 ----
    k_zero_agg<<<aggZeroBlocks, 256>>>(aggElems);
    k_aggregate<<<aggBlocks, 256>>>(h1p, E);
    k_sage_mm<40, false><<<mmGrid, 160, smem40>>>(h1p, Wl2, Wr2, b2, out, N);
}

// round 3
// speedup vs baseline: 1.5819x; 1.5819x over previous
#include <cuda_runtime.h>
#include <math.h>

#define NMAX 100000
#define EMAX 1600000
#define CIN  64

// ---------------- device scratch (no allocation allowed) ----------------
__device__ int   g_is64;
__device__ int   g_src[EMAX];
__device__ int   g_dstE[EMAX];
__device__ int   g_esrc[EMAX];          // CSR: src ids sorted by dst
__device__ int   g_cnt[NMAX];
__device__ int   g_scan[NMAX];
__device__ int   g_bsum[512];
__device__ int   g_boff[512];
__device__ int   g_rowstart[NMAX + 1];
__device__ int   g_cur[NMAX];
__device__ float g_inv[NMAX];
__device__ __align__(256) float g_agg[(size_t)NMAX * 64];
__device__ __align__(256) float g_h0[(size_t)NMAX * 64];
__device__ __align__(256) float g_h1[(size_t)NMAX * 64];
__device__ float g_stats[128];          // [sum(64) | sumsq(64)]
__device__ float g_aff0[128];           // [scale | shift]
__device__ float g_aff1[128];

// ---------------- dtype detection (int64 vs int32 edge_index) ----------------
__global__ void k_detect(const unsigned int* __restrict__ w) {
    int i = threadIdx.x;  // 1024 threads check 2048 odd words
    int ok = (w[2 * i + 1] == 0u) && (w[2 * (i + 1024) + 1] == 0u);
    int all = __syncthreads_and(ok);
    if (i == 0) g_is64 = all ? 1 : 0;
}

__global__ void k_zero_cnt(int N) {
    int i = blockIdx.x * blockDim.x + threadIdx.x;
    if (i < N) g_cnt[i] = 0;
}

// decode edge index + histogram of dst
__global__ void k_decode(const void* __restrict__ ei, int E) {
    int i = blockIdx.x * blockDim.x + threadIdx.x;
    if (i >= E) return;
    int s, d;
    if (g_is64) {
        const long long* p = (const long long*)ei;
        s = (int)p[i];
        d = (int)p[E + i];
    } else {
        const int* p = (const int*)ei;
        s = p[i];
        d = p[E + i];
    }
    g_src[i] = s;
    g_dstE[i] = d;
    atomicAdd(&g_cnt[d], 1);
}

// two-level exclusive scan of g_cnt -> g_rowstart
__global__ void k_scan1(int N) {
    __shared__ int sh[256];
    int i = blockIdx.x * 256 + threadIdx.x;
    int v = (i < N) ? g_cnt[i] : 0;
    sh[threadIdx.x] = v;
    __syncthreads();
    for (int off = 1; off < 256; off <<= 1) {
        int t = (threadIdx.x >= off) ? sh[threadIdx.x - off] : 0;
        __syncthreads();
        sh[threadIdx.x] += t;
        __syncthreads();
    }
    if (i < N) g_scan[i] = sh[threadIdx.x] - v;   // exclusive within block
    if (threadIdx.x == 255) g_bsum[blockIdx.x] = sh[255];
}

__global__ void k_scan2(int NB) {
    __shared__ int sh[512];
    int i = threadIdx.x;
    int v = (i < NB) ? g_bsum[i] : 0;
    sh[i] = v;
    __syncthreads();
    for (int off = 1; off < 512; off <<= 1) {
        int t = (i >= off) ? sh[i - off] : 0;
        __syncthreads();
        sh[i] += t;
        __syncthreads();
    }
    g_boff[i] = sh[i] - v;                         // exclusive
}

__global__ void k_scan3(int N, int E) {
    int i = blockIdx.x * blockDim.x + threadIdx.x;
    if (i < N) {
        int rs = g_scan[i] + g_boff[i >> 8];
        g_rowstart[i] = rs;
        g_cur[i] = rs;
        g_inv[i] = 1.0f / fmaxf((float)g_cnt[i], 1.0f);
    }
    if (i == N) g_rowstart[N] = E;
}

__global__ void k_fill(int E) {
    int i = blockIdx.x * blockDim.x + threadIdx.x;
    if (i >= E) return;
    int d = g_dstE[i];
    int pos = atomicAdd(&g_cur[d], 1);
    g_esrc[pos] = g_src[i];
}

// ---------------- CSR gather aggregation (optionally fused BN+ReLU on input) ----------------
// 16 threads per node, each owns one float4 channel chunk.
template <bool AFFINE>
__global__ void __launch_bounds__(256) k_agg_csr(const float* __restrict__ x,
                                                 const float* __restrict__ aff,
                                                 int N) {
    int t = blockIdx.x * 256 + threadIdx.x;
    int n = t >> 4;
    if (n >= N) return;
    int c = (t & 15) << 2;

    float4 A, B;
    if (AFFINE) {
        A = *reinterpret_cast<const float4*>(aff + c);
        B = *reinterpret_cast<const float4*>(aff + 64 + c);
    }

    int beg = g_rowstart[n];
    int end = g_rowstart[n + 1];
    float4 acc = make_float4(0.f, 0.f, 0.f, 0.f);
#pragma unroll 2
    for (int j = beg; j < end; j++) {
        int s = __ldg(&g_esrc[j]);
        float4 v = *reinterpret_cast<const float4*>(x + (size_t)s * 64 + c);
        if (AFFINE) {
            v.x = fmaxf(fmaf(v.x, A.x, B.x), 0.f);
            v.y = fmaxf(fmaf(v.y, A.y, B.y), 0.f);
            v.z = fmaxf(fmaf(v.z, A.z, B.z), 0.f);
            v.w = fmaxf(fmaf(v.w, A.w, B.w), 0.f);
        }
        acc.x += v.x; acc.y += v.y; acc.z += v.z; acc.w += v.w;
    }
    float inv = g_inv[n];
    acc.x *= inv; acc.y *= inv; acc.z *= inv; acc.w *= inv;
    *reinterpret_cast<float4*>(g_agg + (size_t)n * 64 + c) = acc;
}

// ---------------- fused SAGE linear: out = agg@Wl + f(x)@Wr + b ----------------
// f(x) = relu(bn(x)) when AFFINE, else identity. 4 nodes x 4 out-ch per thread.
template <int COUT, bool STATS, bool AFFINE>
__global__ void __launch_bounds__((COUT / 4) * 16)
k_sage_mm(const float* __restrict__ x,
          const float* __restrict__ aff,
          const float* __restrict__ Wl,
          const float* __restrict__ Wr,
          const float* __restrict__ bias,
          float* __restrict__ out,
          int N) {
    constexpr int CQ = COUT / 4;
    constexpr int NT = 64;
    constexpr int THREADS = CQ * 16;
    constexpr int RS = CIN + 4;

    extern __shared__ float smem[];
    float* sM  = smem;
    float* sX  = sM + NT * RS;
    float* sWl = sX + NT * RS;
    float* sWr = sWl + CIN * COUT;
    float* sSum = sWr + CIN * COUT;
    float* sSq  = sSum + COUT;

    int tid = threadIdx.x;
    for (int i = tid; i < CIN * COUT; i += THREADS) {
        sWl[i] = Wl[i];
        sWr[i] = Wr[i];
    }
    if (STATS) {
        for (int i = tid; i < COUT; i += THREADS) { sSum[i] = 0.0f; sSq[i] = 0.0f; }
    }

    int tile = blockIdx.x * NT;
    for (int q = tid; q < NT * (CIN / 4); q += THREADS) {
        int row = q / (CIN / 4);
        int c4  = (q % (CIN / 4)) * 4;
        int n = tile + row;
        float4 mv, xv;
        if (n < N) {
            mv = *reinterpret_cast<const float4*>(g_agg + (size_t)n * CIN + c4);
            xv = *reinterpret_cast<const float4*>(x + (size_t)n * CIN + c4);
            if (AFFINE) {
                float4 A = *reinterpret_cast<const float4*>(aff + c4);
                float4 B = *reinterpret_cast<const float4*>(aff + 64 + c4);
                xv.x = fmaxf(fmaf(xv.x, A.x, B.x), 0.f);
                xv.y = fmaxf(fmaf(xv.y, A.y, B.y), 0.f);
                xv.z = fmaxf(fmaf(xv.z, A.z, B.z), 0.f);
                xv.w = fmaxf(fmaf(xv.w, A.w, B.w), 0.f);
            }
        } else {
            mv = make_float4(0.f, 0.f, 0.f, 0.f);
            xv = mv;
        }
        *reinterpret_cast<float4*>(sM + row * RS + c4) = mv;
        *reinterpret_cast<float4*>(sX + row * RS + c4) = xv;
    }
    __syncthreads();

    int cog = tid % CQ;
    int ng  = tid / CQ;
    int nb  = ng * 4;

    float acc[4][4];
#pragma unroll
    for (int j = 0; j < 4; j++) {
        float b = bias[cog + j * CQ];
#pragma unroll
        for (int i = 0; i < 4; i++) acc[i][j] = b;
    }

#pragma unroll 4
    for (int k = 0; k < CIN; k++) {
        float wl[4], wr[4], m[4], xr[4];
#pragma unroll
        for (int j = 0; j < 4; j++) {
            wl[j] = sWl[k * COUT + cog + j * CQ];
            wr[j] = sWr[k * COUT + cog + j * CQ];
        }
#pragma unroll
        for (int i = 0; i < 4; i++) {
            m[i]  = sM[(nb + i) * RS + k];
            xr[i] = sX[(nb + i) * RS + k];
        }
#pragma unroll
        for (int i = 0; i < 4; i++)
#pragma unroll
            for (int j = 0; j < 4; j++)
                acc[i][j] += m[i] * wl[j] + xr[i] * wr[j];
    }

    float lsum[4] = {0.f, 0.f, 0.f, 0.f};
    float lsq[4]  = {0.f, 0.f, 0.f, 0.f};
#pragma unroll
    for (int i = 0; i < 4; i++) {
        int n = tile + nb + i;
        if (n < N) {
#pragma unroll
            for (int j = 0; j < 4; j++) {
                float v = acc[i][j];
                out[(size_t)n * COUT + cog + j * CQ] = v;
                if (STATS) { lsum[j] += v; lsq[j] += v * v; }
            }
        }
    }

    if (STATS) {
#pragma unroll
        for (int j = 0; j < 4; j++) {
            atomicAdd(&sSum[cog + j * CQ], lsum[j]);
            atomicAdd(&sSq[cog + j * CQ],  lsq[j]);
        }
        __syncthreads();
        for (int c = tid; c < COUT; c += THREADS) {
            atomicAdd(&g_stats[c],      sSum[c]);
            atomicAdd(&g_stats[64 + c], sSq[c]);
        }
    }
}

__global__ void k_zero_stats() {
    int i = threadIdx.x;
    if (i < 128) g_stats[i] = 0.0f;
}

__global__ void k_bn_finalize(const float* __restrict__ g, const float* __restrict__ be,
                              float invN, float* __restrict__ aff) {
    int c = threadIdx.x;
    if (c < 64) {
        float mu  = g_stats[c] * invN;
        float var = g_stats[64 + c] * invN - mu * mu;
        float a = g[c] * rsqrtf(var + 1e-5f);
        aff[c] = a;
        aff[64 + c] = be[c] - mu * a;
    }
}

// ---------------- launch ----------------
extern "C" void kernel_launch(void* const* d_in, const int* in_sizes, int n_in,
                              void* d_out, int out_size) {
    const float* x   = (const float*)d_in[0];
    const void*  ei  = d_in[1];
    const float* Wl0 = (const float*)d_in[2];
    const float* Wr0 = (const float*)d_in[3];
    const float* b0  = (const float*)d_in[4];
    const float* Wl1 = (const float*)d_in[5];
    const float* Wr1 = (const float*)d_in[6];
    const float* b1  = (const float*)d_in[7];
    const float* Wl2 = (const float*)d_in[8];
    const float* Wr2 = (const float*)d_in[9];
    const float* b2  = (const float*)d_in[10];
    const float* g0  = (const float*)d_in[11];
    const float* be0 = (const float*)d_in[12];
    const float* g1  = (const float*)d_in[13];
    const float* be1 = (const float*)d_in[14];
    float* out = (float*)d_out;

    int N = in_sizes[0] / 64;
    int E = in_sizes[1] / 2;

    float *h0p, *h1p, *aff0p, *aff1p;
    cudaGetSymbolAddress((void**)&h0p, g_h0);
    cudaGetSymbolAddress((void**)&h1p, g_h1);
    cudaGetSymbolAddress((void**)&aff0p, g_aff0);
    cudaGetSymbolAddress((void**)&aff1p, g_aff1);

    const int smem64 = (2 * 64 * (CIN + 4) + 2 * CIN * 64 + 2 * 64) * 4;
    const int smem40 = (2 * 64 * (CIN + 4) + 2 * CIN * 40 + 2 * 40) * 4;
    cudaFuncSetAttribute(k_sage_mm<64, true, false>,
                         cudaFuncAttributeMaxDynamicSharedMemorySize, smem64);
    cudaFuncSetAttribute(k_sage_mm<64, true, true>,
                         cudaFuncAttributeMaxDynamicSharedMemorySize, smem64);
    cudaFuncSetAttribute(k_sage_mm<40, false, true>,
                         cudaFuncAttributeMaxDynamicSharedMemorySize, smem40);

    const int nodeBlocks  = (N + 255) / 256;
    const int nodeBlocks1 = (N + 256) / 256;          // covers i == N
    const int edgeBlocks  = (E + 255) / 256;
    const int NB          = (N + 255) / 256;          // scan blocks
    const int aggBlocks   = (N * 16 + 255) / 256;
    const int mmGrid      = (N + 63) / 64;

    // ---- CSR build (once per launch) ----
    k_detect<<<1, 1024>>>((const unsigned int*)ei);
    k_zero_cnt<<<nodeBlocks, 256>>>(N);
    k_decode<<<edgeBlocks, 256>>>(ei, E);
    k_scan1<<<NB, 256>>>(N);
    k_scan2<<<1, 512>>>(NB);
    k_scan3<<<nodeBlocks1, 256>>>(N, E);
    k_fill<<<edgeBlocks, 256>>>(E);

    // ---- layer 0 ----
    k_agg_csr<false><<<aggBlocks, 256>>>(x, nullptr, N);
    k_zero_stats<<<1, 128>>>();
    k_sage_mm<64, true, false><<<mmGrid, 256, smem64>>>(x, nullptr, Wl0, Wr0, b0, h0p, N);
    k_bn_finalize<<<1, 64>>>(g0, be0, 1.0f / (float)N, aff0p);

    // ---- layer 1 ----
    k_agg_csr<true><<<aggBlocks, 256>>>(h0p, aff0p, N);
    k_zero_stats<<<1, 128>>>();
    k_sage_mm<64, true, true><<<mmGrid, 256, smem64>>>(h0p, aff0p, Wl1, Wr1, b1, h1p, N);
    k_bn_finalize<<<1, 64>>>(g1, be1, 1.0f / (float)N, aff1p);

    // ---- layer 2 ----
    k_agg_csr<true><<<aggBlocks, 256>>>(h1p, aff1p, N);
    k_sage_mm<40, false, true><<<mmGrid, 160, smem40>>>(h1p, aff1p, Wl2, Wr2, b2, out, N);
}